// round 5
// baseline (speedup 1.0000x reference)
#include <cuda_runtime.h>
#include <cuda_bf16.h>

// FasterPConv: B=2, N=80000, K=16 neighbors, C=32 channels, H=4 heads, M=8 mid.
// out[b,n,m,c] = sum_k feat[b, idx[b,n,k], c] * guid[b,n,k, c/(C/H)] * w[b,n,k,m]
//
// One warp per point n. lane = channel c.
//   - neighbor row = 32 fp32 = 128 B -> one coalesced transaction per k
//   - weightnet (K*M=128 f32) + guidance (K*H=64 f32) staged to shared per
//     warp via vectorized loads, consumed as broadcasts (conflict-free)
//   - indices hoisted to registers before the k-loop so all 16 gather LDGs
//     front-batch (max MLP)
//   - 8 accumulators/lane, 8 coalesced 128 B output stores per warp

constexpr int C = 32;
constexpr int K = 16;
constexpr int H = 4;
constexpr int M = 8;
constexpr int WARPS_PER_BLOCK = 8;
constexpr int THREADS = WARPS_PER_BLOCK * 32;

__global__ __launch_bounds__(THREADS)
void fasterpconv_kernel(const float* __restrict__ feat,
                        const int* __restrict__ inds,
                        const float* __restrict__ guid,
                        const float* __restrict__ wn,
                        float* __restrict__ out,
                        int BN, int N) {
    __shared__ float sw[WARPS_PER_BLOCK][K * M];   // 128 f32 per warp
    __shared__ float sg[WARPS_PER_BLOCK][K * H];   // 64 f32 per warp
    __shared__ int   sidx[WARPS_PER_BLOCK][K];     // 16 i32 per warp

    const int w    = threadIdx.x >> 5;
    const int lane = threadIdx.x & 31;
    const int p    = blockIdx.x * WARPS_PER_BLOCK + w;   // point index in [0, B*N)
    if (p >= BN) return;

    // ---- stage per-point small tensors into shared (vectorized) ----
    {
        // weightnet: 128 floats = 32 float4 -> one float4 per lane
        const float4* wsrc = reinterpret_cast<const float4*>(wn + (size_t)p * (K * M));
        reinterpret_cast<float4*>(sw[w])[lane] = wsrc[lane];
        // guidance: 64 floats = 16 float4 -> lanes 0..15; indices: lanes 0..15
        if (lane < 16) {
            const float4* gsrc = reinterpret_cast<const float4*>(guid + (size_t)p * (K * H));
            reinterpret_cast<float4*>(sg[w])[lane] = gsrc[lane];
            sidx[w][lane] = inds[(size_t)p * K + lane];
        }
    }
    __syncwarp();

    // b = p / N with B=2: branch-free compare instead of integer division.
    const size_t batch_off = (p >= N) ? (size_t)N * C : 0;
    const float* fbase = feat + batch_off + lane;

    // Hoist all 16 indices to registers (one LDS batch), so the 16 gather
    // LDGs below have no LDS in their dependency chain and front-batch.
    int idxr[K];
#pragma unroll
    for (int k = 0; k < K; k++) idxr[k] = sidx[w][k];

    float acc[M];
#pragma unroll
    for (int m = 0; m < M; m++) acc[m] = 0.0f;

    const int head = lane >> 3;   // c / (C/H) with C/H = 8

    // Front-batch the gathers for max MLP.
    float fv[K];
#pragma unroll
    for (int k = 0; k < K; k++) {
        fv[k] = __ldg(fbase + (size_t)idxr[k] * C);
    }

#pragma unroll
    for (int k = 0; k < K; k++) {
        const float v = fv[k] * sg[w][k * H + head];
#pragma unroll
        for (int m = 0; m < M; m++) {
            acc[m] = fmaf(v, sw[w][k * M + m], acc[m]);
        }
    }

    // ---- write out[p, m, c] : 8 coalesced 128B stores per warp ----
    float* op = out + (size_t)p * (M * C) + lane;
#pragma unroll
    for (int m = 0; m < M; m++) {
        op[m * C] = acc[m];
    }
}

extern "C" void kernel_launch(void* const* d_in, const int* in_sizes, int n_in,
                              void* d_out, int out_size) {
    const float* feat = (const float*)d_in[0];   // [B,N,C]
    const int*   inds = (const int*)d_in[1];     // [B,N,K]
    const float* guid = (const float*)d_in[2];   // [B,N,K,H]
    const float* wn   = (const float*)d_in[3];   // [B,N,K,M]
    float* out = (float*)d_out;                  // [B,N,M*C]

    const int BN = in_sizes[1] / K;              // B*N points total
    const int N  = (in_sizes[0] / C) / 2;        // per-batch N (B=2)

    const int blocks = (BN + WARPS_PER_BLOCK - 1) / WARPS_PER_BLOCK;
    fasterpconv_kernel<<<blocks, THREADS>>>(feat, inds, guid, wn, out, BN, N);
}